// round 9
// baseline (speedup 1.0000x reference)
#include <cuda_runtime.h>
#include <cuda_fp16.h>

#define BB 2
#define FIN 128
#define NN 192
#define SS 192
#define HH 4
#define DD 64
#define CC 256          // H*D
#define NEG 0.2f
#define TOTF 73728.0f   // B*S*N
#define L2E 1.44269504088896f
#define CH 6            // n per attn block -> 32*4*2 = 256 blocks
#define TPA 576
#define EPH 97          // half2 pitch for slab rows (odd -> conflict-free)

// smem word offsets (fp32 words)
#define W_SLAB 0        // half2 [192 s][97 pairs]          18624
#define W_SVC  18624    // u32(half2) [6][192] compacted src 1152
#define W_SOFS 19776    // u32 [6][192] byte offsets         1152
#define W_PART 20928    // 1152: p1 float2[6][96] / p2 f32[6][192]
#define W_RDEN 22080    // float2[96]                         192
#define W_APH  22272    // f32[192]                           192
#define W_SGS  22464    // f32[64]                             64
#define W_SLOT 22528    // uchar[6][192]                      288
#define W_CNT  22816    // int cnt[6] + wcnt[36]               44
#define W_TOT  22860    // 91440 B -> 2 blocks/SM

__device__ __forceinline__ __half2 h2ex2(__half2 x) {
    unsigned r, xi = *reinterpret_cast<unsigned*>(&x);
    asm("ex2.approx.f16x2 %0, %1;" : "=r"(r) : "r"(xi));
    return *reinterpret_cast<__half2*>(&r);
}

// ---------------- scratch ----------------
__device__ float d_u[2][HH][FIN];
__device__ float d_c[2][HH];
__device__ float d_sumx[BB * FIN];
__device__ float d_SsrcP[2][BB][HH][NN][SS];  // f-half partials, pre-scaled log2e
__device__ float d_SdstP[2][BB][HH][NN][SS];

// ---------------- K0 ----------------
__global__ void k_prep(const float* __restrict__ W_lin,
                       const float* __restrict__ b_lin,
                       const float* __restrict__ W_attn) {
    int f = threadIdx.x;  // 128
    #pragma unroll
    for (int h = 0; h < HH; h++) {
        float as = 0.f, ad = 0.f;
        #pragma unroll 8
        for (int d = 0; d < DD; d++) {
            float w = W_lin[f * CC + h * DD + d];
            as += w * W_attn[d];
            ad += w * W_attn[DD + d];
        }
        d_u[0][h][f] = as;
        d_u[1][h][f] = ad;
    }
    if (f < HH) {
        int h = f;
        float cs = 0.f, cd = 0.f;
        for (int d = 0; d < DD; d++) {
            cs += b_lin[h * DD + d] * W_attn[d];
            cd += b_lin[h * DD + d] * W_attn[DD + d];
        }
        d_c[0][h] = cs;
        d_c[1][h] = cd;
    }
}

// ---------------- K1: projections, float2 over s, 2 n per block ----------------
// grid (96, 2, BB), block 192
__global__ void __launch_bounds__(192) k_proj(const float* __restrict__ X,
                                              const float* __restrict__ b_attn) {
    __shared__ float su[2][HH][64];
    int tid = threadIdx.x;
    int half = blockIdx.y, b = blockIdx.z;
    for (int i = tid; i < 2 * HH * 64; i += 192) {
        int t = i / (HH * 64), r = i % (HH * 64);
        su[t][r / 64][r % 64] = d_u[t][r / 64][half * 64 + (r % 64)];
    }
    __syncthreads();

    int s2 = tid % 96, nn = tid / 96;
    int n = blockIdx.x * 2 + nn;
    float as[2][HH], ad[2][HH];
    #pragma unroll
    for (int j = 0; j < 2; j++)
        #pragma unroll
        for (int h = 0; h < HH; h++) { as[j][h] = 0.f; ad[j][h] = 0.f; }

    const float2* Xp = (const float2*)(X + (((size_t)b * FIN + half * 64) * NN + n) * SS) + s2;
    const size_t FST2 = (size_t)NN * SS / 2;

    #pragma unroll
    for (int f0 = 0; f0 < 64; f0 += 16) {
        float2 xv[16];
        #pragma unroll
        for (int k = 0; k < 16; k++) xv[k] = Xp[(f0 + k) * FST2];
        #pragma unroll
        for (int k = 0; k < 16; k++) {
            #pragma unroll
            for (int h = 0; h < HH; h++) {
                float wu = su[0][h][f0 + k], wd = su[1][h][f0 + k];
                as[0][h] += xv[k].x * wu;  ad[0][h] += xv[k].x * wd;
                as[1][h] += xv[k].y * wu;  ad[1][h] += xv[k].y * wd;
            }
        }
    }
    float cb = b_attn[0];
    #pragma unroll
    for (int h = 0; h < HH; h++) {
        float cs = (half == 0) ? (d_c[0][h] + cb) : 0.f;
        float cd = (half == 0) ? d_c[1][h] : 0.f;
        float2 vs = make_float2((as[0][h] + cs) * L2E, (as[1][h] + cs) * L2E);
        float2 vd = make_float2((ad[0][h] + cd) * L2E, (ad[1][h] + cd) * L2E);
        ((float2*)&d_SsrcP[half][b][h][n][0])[s2] = vs;
        ((float2*)&d_SdstP[half][b][h][n][0])[s2] = vd;
    }
}

// ---------------- K2: X row sums ----------------
__global__ void k_sumx(const float* __restrict__ X) {
    int bf = blockIdx.x;  // 256 blocks
    const float4* p = (const float4*)(X + (size_t)bf * (NN * SS));
    float acc = 0.f;
    for (int i = threadIdx.x; i < NN * SS / 4; i += 256) {
        float4 v = p[i];
        acc += (v.x + v.y) + (v.z + v.w);
    }
    __shared__ float sm[256];
    sm[threadIdx.x] = acc;
    __syncthreads();
    #pragma unroll
    for (int st = 128; st > 0; st >>= 1) {
        if (threadIdx.x < st) sm[threadIdx.x] += sm[threadIdx.x + st];
        __syncthreads();
    }
    if (threadIdx.x == 0) d_sumx[bf] = sm[0];
}

// ---------------- K3: fused attention + sum_g + output ----------------
// grid (32, HH, BB) = 256 blocks, block 576, 2 blocks/SM.
__global__ void __launch_bounds__(TPA, 2) k_attn(const int* __restrict__ A,
                                                 const float* __restrict__ W_lin,
                                                 const float* __restrict__ b_lin,
                                                 float* __restrict__ out) {
    extern __shared__ float smem[];
    __half*        slabh = (__half*)(smem + W_SLAB);   // [s][194 halves]
    __half2*       slab2 = (__half2*)(smem + W_SLAB);  // [s][EPH]
    unsigned*      svc   = (unsigned*)(smem + W_SVC);  // [6][192] compacted half2
    unsigned*      sofs  = (unsigned*)(smem + W_SOFS); // [6][192] byte offsets
    float*         part  = smem + W_PART;
    float2*        part2 = (float2*)part;
    float2*        rden2 = (float2*)(smem + W_RDEN);
    float*         aph   = smem + W_APH;
    float*         sgs   = smem + W_SGS;
    unsigned char* slot  = (unsigned char*)(smem + W_SLOT);
    int*           cnt   = (int*)(smem + W_CNT);
    int*           wcnt  = cnt + 6;

    int tid = threadIdx.x;
    int h = blockIdx.y, b = blockIdx.z;
    int nbase = blockIdx.x * CH;
    const __half2 neg2 = __float2half2_rn(NEG);
    const __half2 zero2 = __float2half2_rn(0.f);

    // ---- prologue A: slab staging, mask ballots, sum_g partials ----
    {
        const float4* p0 = (const float4*)&d_SdstP[0][b][h][0][0];
        const float4* p1 = (const float4*)&d_SdstP[1][b][h][0][0];
        #pragma unroll
        for (int i = tid; i < NN * SS / 4; i += TPA) {
            float4 v0 = p0[i], v1 = p1[i];
            int e = i * 4;
            int m = e / SS, s = e % SS;
            slabh[(s    ) * 194 + m] = __float2half(v0.x + v1.x);
            slabh[(s + 1) * 194 + m] = __float2half(v0.y + v1.y);
            slabh[(s + 2) * 194 + m] = __float2half(v0.z + v1.z);
            slabh[(s + 3) * 194 + m] = __float2half(v0.w + v1.w);
        }
    }
    unsigned bals[CH];
    int mkbits = 0;
    if (tid < SS) {
        #pragma unroll
        for (int ni = 0; ni < CH; ni++) {
            int mk = (A[tid * NN + nbase + ni] != 0);
            unsigned bal = __ballot_sync(0xFFFFFFFFu, mk);
            bals[ni] = bal;
            mkbits |= mk << ni;
            if ((tid & 31) == 0) wcnt[ni * 6 + (tid >> 5)] = __popc(bal);
        }
    }
    if (tid >= 64) {  // 512 threads: sum_g partials (temp in part)
        int t = tid - 64, d = t >> 3, k = t & 7;
        float acc = 0.f;
        const float* wp = W_lin + h * 64 + d;
        #pragma unroll
        for (int f = k * 16; f < k * 16 + 16; f++)
            acc += (d_sumx[f] + d_sumx[FIN + f]) * wp[f * CC];
        part[t] = acc;
    }
    __syncthreads();

    // ---- prologue B: compacted tables + counts + sgs ----
    if (tid < SS) {
        int w = tid >> 5, l = tid & 31;
        unsigned lmask = (1u << l) - 1u;
        #pragma unroll
        for (int ni = 0; ni < CH; ni++) {
            float v = d_SsrcP[0][b][h][nbase + ni][tid]
                    + d_SsrcP[1][b][h][nbase + ni][tid];
            if ((mkbits >> ni) & 1) {
                int base = 0;
                #pragma unroll
                for (int q = 0; q < 5; q++) base += (q < w) ? wcnt[ni * 6 + q] : 0;
                int pos = base + __popc(bals[ni] & lmask);
                __half2 hv = __float2half2_rn(v);
                svc[ni * 192 + pos] = *reinterpret_cast<unsigned*>(&hv);
                sofs[ni * 192 + pos] = (unsigned)(tid * EPH * 4);
                slot[ni * 192 + tid] = (unsigned char)pos;
            } else {
                slot[ni * 192 + tid] = 255;
            }
        }
    }
    if (tid >= 192 && tid < 192 + CH) {
        int ni = tid - 192;
        cnt[ni] = wcnt[ni * 6] + wcnt[ni * 6 + 1] + wcnt[ni * 6 + 2]
                + wcnt[ni * 6 + 3] + wcnt[ni * 6 + 4] + wcnt[ni * 6 + 5];
    }
    __syncthreads();
    if (tid >= 256 && tid < 320) {
        int d = tid - 256;
        float s = 0.f;
        #pragma unroll
        for (int k = 0; k < 8; k++) s += part[d * 8 + k];
        sgs[d] = s + TOTF * b_lin[h * 64 + d];
    }
    __syncthreads();

    int p1p = tid % 96, jj = tid / 96;   // pass1: m-pair, s-chunk(6)
    int u = tid % 96, v = tid / 96;      // pass2: slot-col, 16-pair chunk(6)
    size_t cb0 = (size_t)b * CC + h * 64;
    float4* outp = (float4*)out;
    const char* slabB = (const char*)slab2;

    for (int ni = 0; ni < CH; ni++) {
        int c = cnt[ni];
        const unsigned* svcn = svc + ni * 192;
        const unsigned* sofn = sofs + ni * 192;

        // pass 1: denom partials, compacted s, half2 flush-4 accumulate
        {
            const char* myB = slabB + p1p * 4;
            int i0 = (c * jj) / 6, i1 = (c * (jj + 1)) / 6;
            float ax = 0.f, ay = 0.f;
            int i = i0;
            for (; i + 4 <= i1; i += 4) {
                __half2 hacc = zero2;
                #pragma unroll
                for (int k = 0; k < 4; k++) {
                    unsigned sv = svcn[i + k];
                    unsigned of = sofn[i + k];
                    __half2 t = __hadd2(*reinterpret_cast<__half2*>(&sv),
                                        *(const __half2*)(myB + of));
                    t = __hmax2(t, __hmul2(t, neg2));
                    hacc = __hadd2(hacc, h2ex2(t));
                }
                float2 f = __half22float2(hacc);
                ax += f.x; ay += f.y;
            }
            for (; i < i1; i++) {
                unsigned sv = svcn[i];
                unsigned of = sofn[i];
                __half2 t = __hadd2(*reinterpret_cast<__half2*>(&sv),
                                    *(const __half2*)(myB + of));
                t = __hmax2(t, __hmul2(t, neg2));
                float2 f = __half22float2(h2ex2(t));
                ax += f.x; ay += f.y;
            }
            part2[jj * 96 + p1p] = make_float2(ax, ay);
        }
        __syncthreads();
        if (tid < 96) {
            float dx = 0.f, dy = 0.f;
            #pragma unroll
            for (int q = 0; q < 6; q++) {
                float2 w = part2[q * 96 + tid];
                dx += w.x; dy += w.y;
            }
            rden2[tid] = make_float2(dx > 0.f ? __fdividef(1.f, dx) : 0.f,
                                     dy > 0.f ? __fdividef(1.f, dy) : 0.f);
        }
        // overlap: output of previous n
        if (ni > 0) {
            int nOut = nbase + ni - 1;
            #pragma unroll
            for (int idx = tid; idx < 64 * 48; idx += TPA) {
                int d = idx / 48, s4 = idx - d * 48;
                float g = sgs[d];
                float4 a = ((const float4*)aph)[s4];
                outp[((cb0 + d) * NN + nOut) * 48 + s4] =
                    make_float4(a.x * g, a.y * g, a.z * g, a.w * g);
            }
        }
        __syncthreads();

        // pass 2: alpha partials. thread covers slots u and u+96, pairs [16v,16v+16)
        {
            float r0 = 0.f, r1 = 0.f;
            const float2* rd = rden2 + v * 16;
            if (u < c) {
                unsigned svr = svcn[u];
                __half2 sv = *reinterpret_cast<__half2*>(&svr);
                const __half2* row = (const __half2*)(slabB + sofn[u]) + v * 16;
                #pragma unroll
                for (int q = 0; q < 16; q++) {
                    __half2 t = __hadd2(sv, row[q]);
                    t = __hmax2(t, __hmul2(t, neg2));
                    float2 ef = __half22float2(h2ex2(t));
                    float2 r = rd[q];
                    r0 += ef.x * r.x + ef.y * r.y;
                }
            }
            if (u + 96 < c) {
                unsigned svr = svcn[u + 96];
                __half2 sv = *reinterpret_cast<__half2*>(&svr);
                const __half2* row = (const __half2*)(slabB + sofn[u + 96]) + v * 16;
                #pragma unroll
                for (int q = 0; q < 16; q++) {
                    __half2 t = __hadd2(sv, row[q]);
                    t = __hmax2(t, __hmul2(t, neg2));
                    float2 ef = __half22float2(h2ex2(t));
                    float2 r = rd[q];
                    r1 += ef.x * r.x + ef.y * r.y;
                }
            }
            part[v * 192 + u] = r0;
            part[v * 192 + 96 + u] = r1;
        }
        __syncthreads();
        if (tid < SS) {
            int k = slot[ni * 192 + tid];
            float s = 0.f;
            if (k != 255) {
                #pragma unroll
                for (int q = 0; q < 6; q++) s += part[q * 192 + k];
            }
            aph[tid] = s;
        }
        __syncthreads();
    }
    // final output (n = nbase + CH - 1)
    {
        int nOut = nbase + CH - 1;
        #pragma unroll
        for (int idx = tid; idx < 64 * 48; idx += TPA) {
            int d = idx / 48, s4 = idx - d * 48;
            float g = sgs[d];
            float4 a = ((const float4*)aph)[s4];
            outp[((cb0 + d) * NN + nOut) * 48 + s4] =
                make_float4(a.x * g, a.y * g, a.z * g, a.w * g);
        }
    }
}

extern "C" void kernel_launch(void* const* d_in, const int* in_sizes, int n_in,
                              void* d_out, int out_size) {
    const float* X      = (const float*)d_in[0];
    const int*   A      = (const int*)  d_in[1];
    const float* W_lin  = (const float*)d_in[2];
    const float* b_lin  = (const float*)d_in[3];
    const float* W_attn = (const float*)d_in[4];
    const float* b_attn = (const float*)d_in[5];
    float* out = (float*)d_out;

    const int SMEM_ATTN = W_TOT * 4;  // 91440 B
    cudaFuncSetAttribute(k_attn, cudaFuncAttributeMaxDynamicSharedMemorySize, SMEM_ATTN);

    k_prep<<<1, 128>>>(W_lin, b_lin, W_attn);
    k_proj<<<dim3(96, 2, BB), 192>>>(X, b_attn);
    k_sumx<<<BB * FIN, 256>>>(X);
    k_attn<<<dim3(NN / CH, HH, BB), TPA, SMEM_ATTN>>>(A, W_lin, b_lin, out);
}